// round 15
// baseline (speedup 1.0000x reference)
#include <cuda_runtime.h>
#include <cstdint>

#define B_      128
#define G_      10000
#define KW_     20
#define GC_     30000
#define LAT_    2000
#define INLEN_  200000

#define KSPLIT  15
#define KCHUNK  2016          // 15*2016 >= 30000; 2016%32==0
#define ZLD     2048

#define BK      32
#define SAK     36            // padded row stride (floats) -> conflict-free frags
#define A_TILE_F (128 * SAK)
#define W_TILE_F (64 * SAK)
#define STAGE_F  (A_TILE_F + W_TILE_F)
#define STAGE_BYTES (STAGE_F * 4)         // 27648
#define NST     2
#define SMEM_DYN (NST * STAGE_BYTES)      // 55296 -> 3 CTAs/SM

// ----- scratch (static device globals; allocation-free rule) -----
__device__ float g_h[B_ * GC_];
__device__ float g_zpart[KSPLIT * B_ * ZLD];
__device__ float g_z[B_ * LAT_];
__device__ float g_d[B_ * GC_];

__device__ __forceinline__ float lrelu(float v) { return v >= 0.0f ? v : 0.1f * v; }

__device__ __forceinline__ uint32_t smem_u32(const void* p) {
    return (uint32_t)__cvta_generic_to_shared(p);
}
__device__ __forceinline__ void cp_async16(uint32_t dst, const void* src, int sz) {
    asm volatile("cp.async.cg.shared.global [%0], [%1], 16, %2;"
                 :: "r"(dst), "l"(src), "r"(sz));
}
#define CP_COMMIT() asm volatile("cp.async.commit_group;" ::: "memory")
#define CP_WAIT1()  asm volatile("cp.async.wait_group 1;" ::: "memory")
#define CP_WAIT0()  asm volatile("cp.async.wait_group 0;" ::: "memory")

// raw fp32 bits fed as tf32 operands (HW truncation; measured 4.3e-6 final err)
__device__ __forceinline__ void mma_tf32(float c[4], uint32_t a0, uint32_t a1,
                                         uint32_t a2, uint32_t a3,
                                         uint32_t b0, uint32_t b1) {
    asm volatile(
        "mma.sync.aligned.m16n8k8.row.col.f32.tf32.tf32.f32 "
        "{%0,%1,%2,%3}, {%4,%5,%6,%7}, {%8,%9}, {%0,%1,%2,%3};"
        : "+f"(c[0]), "+f"(c[1]), "+f"(c[2]), "+f"(c[3])
        : "r"(a0), "r"(a1), "r"(a2), "r"(a3), "r"(b0), "r"(b1));
}

// ---------------------------------------------------------------------------
// K1: encoder grouped conv
// ---------------------------------------------------------------------------
__global__ void __launch_bounds__(192)
enc_conv_kernel(const float* __restrict__ x, const float* __restrict__ ew,
                const float* __restrict__ eb) {
    __shared__ float sx[64 * KW_];
    const int b  = blockIdx.y;
    const int g0 = blockIdx.x * 64;
    const int ng = (G_ - g0 < 64) ? (G_ - g0) : 64;
    const int nval = ng * KW_;
    for (int i = threadIdx.x; i < nval; i += 192)
        sx[i] = x[(size_t)b * INLEN_ + (size_t)g0 * KW_ + i];
    __syncthreads();
    const int j  = threadIdx.x;
    const int gl = j / 3;
    const int c  = j - gl * 3;
    const int g  = g0 + gl;
    if (gl < ng) {
        const float* w  = ew + (size_t)g * 60 + c * 20;
        const float* xv = sx + gl * KW_;
        float acc = eb[g * 3 + c];
#pragma unroll
        for (int k = 0; k < KW_; k++) acc = fmaf(xv[k], w[k], acc);
        g_h[(size_t)b * GC_ + g * 3 + c] = lrelu(acc);
    }
}

// ---------------------------------------------------------------------------
// tf32 mma.sync GEMM: C[128, 64-tile] (+)= A[128,K] x W[N,K]^T
// Block tile 128x64x32, warp grid 2(M)x4(N), warp tile 64x16 -> 32 acc regs,
// R11-proven scalar LDS.32 fragment loads, 2-stage cp.async, 3 CTAs/SM.
//   mode 0: A=g_h, C=g_zpart + by*B_*ZLD (raw split-K partial)
//   mode 1: A=g_z, C=g_d, epilogue lrelu(acc + bias[n])
// ---------------------------------------------------------------------------
__global__ void __launch_bounds__(256, 3)
gemm_tc(const float* __restrict__ Wg, const float* __restrict__ bias,
        int lda, int ldw, int ldc, int Ntot, int Ktot, int mode)
{
    extern __shared__ float smem[];
    const int tid  = threadIdx.x;
    const int lane = tid & 31;
    const int wid  = tid >> 5;
    const int gq   = lane >> 2;    // 0..7
    const int tg   = lane & 3;     // 0..3
    const int wm   = wid >> 2;     // 0..1  (M: 64-row halves)
    const int wn   = wid & 3;      // 0..3  (N: 16-col slices)

    const int n0 = blockIdx.x * 64;
    const int k0 = blockIdx.y * KCHUNK;
    const int k1 = (k0 + KCHUNK < Ktot) ? (k0 + KCHUNK) : Ktot;
    const int T  = (k1 - k0 + BK - 1) >> 5;

    const float* A = (mode == 0) ? g_h : g_z;
    float* C = (mode == 0) ? (g_zpart + (size_t)blockIdx.y * (B_ * (size_t)ZLD))
                           : g_d;

    const uint32_t sbase = smem_u32(smem);

    // loader: A 1024 segs (4/thread), W 512 segs (2/thread); 16B each.
    auto load_tile = [&](int t, int s) {
        const int kb = k0 + (t << 5);
        const uint32_t sa = sbase + (uint32_t)s * STAGE_BYTES;
        const uint32_t sw = sa + A_TILE_F * 4;
#pragma unroll
        for (int u = 0; u < 4; u++) {
            const int f   = tid + u * 256;
            const int row = f >> 3;
            const int seg = f & 7;
            const int kk  = kb + seg * 4;
            const int ok  = (kk + 4 <= k1) ? 16 : 0;
            cp_async16(sa + (uint32_t)(row * (SAK * 4) + seg * 16),
                       ok ? (A + (size_t)row * lda + kk) : A, ok);
        }
#pragma unroll
        for (int u = 0; u < 2; u++) {
            const int f   = tid + u * 256;
            const int row = f >> 3;         // 0..63
            const int seg = f & 7;
            const int kk  = kb + seg * 4;
            const int n   = n0 + row;
            const int ok  = (kk + 4 <= k1 && n < Ntot) ? 16 : 0;
            cp_async16(sw + (uint32_t)(row * (SAK * 4) + seg * 16),
                       ok ? (Wg + (size_t)n * ldw + kk) : Wg, ok);
        }
        CP_COMMIT();
    };

    float acc[4][2][4];
#pragma unroll
    for (int i = 0; i < 4; i++)
#pragma unroll
        for (int j = 0; j < 2; j++)
#pragma unroll
            for (int r = 0; r < 4; r++) acc[i][j][r] = 0.0f;

    load_tile(0, 0);
    if (T > 1) load_tile(1, 1);

    for (int t = 0; t < T; t++) {
        if (t + 1 < T) { CP_WAIT1(); } else { CP_WAIT0(); }
        __syncthreads();

        const float* As = smem + (size_t)(t & 1) * STAGE_F;
        const float* Ws = As + A_TILE_F;
#pragma unroll
        for (int ks = 0; ks < 4; ks++) {
            const int kk0 = ks * 8;
            uint32_t af[4][4];
#pragma unroll
            for (int i = 0; i < 4; i++) {
                const float* ap = As + (size_t)(wm * 64 + i * 16 + gq) * SAK
                                + kk0 + tg;
                af[i][0] = __float_as_uint(ap[0]);
                af[i][2] = __float_as_uint(ap[4]);
                af[i][1] = __float_as_uint(ap[8 * SAK]);
                af[i][3] = __float_as_uint(ap[8 * SAK + 4]);
            }
#pragma unroll
            for (int j = 0; j < 2; j++) {
                const float* wp = Ws + (size_t)(wn * 16 + j * 8 + gq) * SAK
                                + kk0 + tg;
                const uint32_t b0 = __float_as_uint(wp[0]);
                const uint32_t b1 = __float_as_uint(wp[4]);
#pragma unroll
                for (int i = 0; i < 4; i++)
                    mma_tf32(acc[i][j], af[i][0], af[i][1], af[i][2], af[i][3],
                             b0, b1);
            }
        }
        __syncthreads();
        if (t + 2 < T) load_tile(t + 2, t & 1);
    }

    // epilogue
#pragma unroll
    for (int i = 0; i < 4; i++) {
        const int row = wm * 64 + i * 16 + gq;
#pragma unroll
        for (int j = 0; j < 2; j++) {
            const int col = n0 + wn * 16 + j * 8 + 2 * tg;
            float v0 = acc[i][j][0], v1 = acc[i][j][1];
            float v2 = acc[i][j][2], v3 = acc[i][j][3];
            if (mode == 1) {
                if (col >= Ntot) continue;
                const float b0 = bias[col], b1 = bias[col + 1];
                v0 = lrelu(v0 + b0); v1 = lrelu(v1 + b1);
                v2 = lrelu(v2 + b0); v3 = lrelu(v3 + b1);
            }
            *(float2*)(C + (size_t)row * ldc + col) = make_float2(v0, v1);
            *(float2*)(C + (size_t)(row + 8) * ldc + col) = make_float2(v2, v3);
        }
    }
}

// ---------------------------------------------------------------------------
// K3: split-K reduce + bias + leaky -> g_z
// ---------------------------------------------------------------------------
__global__ void __launch_bounds__(256)
reduce_z(const float* __restrict__ bias) {
    int idx = blockIdx.x * 256 + threadIdx.x;
    if (idx >= B_ * LAT_) return;
    int b = idx / LAT_;
    int n = idx - b * LAT_;
    float s = bias[n];
#pragma unroll
    for (int sp = 0; sp < KSPLIT; sp++)
        s += g_zpart[(size_t)sp * B_ * ZLD + (size_t)b * ZLD + n];
    g_z[idx] = lrelu(s);
}

// ---------------------------------------------------------------------------
// K5: decoder grouped conv-transpose + sigmoid (float4 vectorized)
// ---------------------------------------------------------------------------
__global__ void __launch_bounds__(256)
dec_kernel(const float* __restrict__ dw, const float* __restrict__ db,
           float* __restrict__ out) {
    int idx = blockIdx.x * 256 + threadIdx.x;
    if (idx >= B_ * G_ * 5) return;
    int b = idx / (G_ * 5);
    int r = idx - b * (G_ * 5);
    int g = r / 5;
    int q = (r - g * 5) * 4;

    const float* dd = g_d + (size_t)b * GC_ + g * 3;
    const float d0 = dd[0], d1 = dd[1], d2 = dd[2];
    const float* wb = dw + (size_t)g * 60 + q;
    const float4 w0 = *(const float4*)(wb);
    const float4 w1 = *(const float4*)(wb + 20);
    const float4 w2 = *(const float4*)(wb + 40);
    const float bs = db[g];

    float4 o;
    float a;
    a = bs + d0 * w0.x + d1 * w1.x + d2 * w2.x; o.x = 1.0f / (1.0f + __expf(-a));
    a = bs + d0 * w0.y + d1 * w1.y + d2 * w2.y; o.y = 1.0f / (1.0f + __expf(-a));
    a = bs + d0 * w0.z + d1 * w1.z + d2 * w2.z; o.z = 1.0f / (1.0f + __expf(-a));
    a = bs + d0 * w0.w + d1 * w1.w + d2 * w2.w; o.w = 1.0f / (1.0f + __expf(-a));
    *(float4*)(out + (size_t)b * INLEN_ + g * 20 + q) = o;
}

// ---------------------------------------------------------------------------
extern "C" void kernel_launch(void* const* d_in, const int* in_sizes, int n_in,
                              void* d_out, int out_size) {
    const float* x        = (const float*)d_in[0];
    const float* enc_w    = (const float*)d_in[1];
    const float* enc_b    = (const float*)d_in[2];
    const float* enc_fc_w = (const float*)d_in[3];
    const float* enc_fc_b = (const float*)d_in[4];
    const float* dec_fc_w = (const float*)d_in[5];
    const float* dec_fc_b = (const float*)d_in[6];
    const float* dec_w    = (const float*)d_in[7];
    const float* dec_b    = (const float*)d_in[8];
    float* out = (float*)d_out;

    cudaFuncSetAttribute(gemm_tc, cudaFuncAttributeMaxDynamicSharedMemorySize,
                         SMEM_DYN);

    // 1) encoder grouped conv -> g_h [128, 30000]
    enc_conv_kernel<<<dim3(157, 128), 192>>>(x, enc_w, enc_b);

    // 2) enc FC tf32 mma, split-K=15 -> g_zpart  (W=[2000,30000])
    //    N-tiles of 64: 32 tiles cover 2048 (ZLD-padded, zero-filled >2000)
    gemm_tc<<<dim3(32, KSPLIT), 256, SMEM_DYN>>>(enc_fc_w, nullptr,
                                                 GC_, GC_, ZLD, LAT_, GC_, 0);

    // 3) reduce + bias + leaky -> g_z [128, 2000]
    reduce_z<<<(B_ * LAT_ + 255) / 256, 256>>>(enc_fc_b);

    // 4) dec FC tf32 mma, fused epilogue -> g_d [128, 30000]  (W=[30000,2000])
    gemm_tc<<<dim3((GC_ + 63) / 64, 1), 256, SMEM_DYN>>>(dec_fc_w, dec_fc_b,
                                                         LAT_, LAT_, GC_, GC_,
                                                         LAT_, 1);

    // 5) decoder conv-transpose + sigmoid -> out [128, 200000]
    dec_kernel<<<(B_ * G_ * 5 + 255) / 256, 256>>>(dec_w, dec_b, out);
}

// round 16
// speedup vs baseline: 1.1945x; 1.1945x over previous
#include <cuda_runtime.h>
#include <cstdint>

#define B_      128
#define G_      10000
#define KW_     20
#define GC_     30000
#define LAT_    2000
#define INLEN_  200000

#define KSPLIT  15
#define KCHUNK  2016          // 15*2016 >= 30000; 2016%32==0
#define ZLD     2048

#define BK      32
#define SAK     36            // padded row stride (floats) -> conflict-free frags
#define TILE_F  (128 * SAK)   // floats per operand tile
#define TILE_B  (TILE_F * 4)  // 18432 bytes
#define NST     3
#define STAGE_BYTES (2 * TILE_B)          // A + W  (36864)
#define SMEM_DYN    (NST * STAGE_BYTES)   // 110592 -> 2 CTAs/SM

// ----- scratch (static device globals; allocation-free rule) -----
__device__ float g_h[B_ * GC_];
__device__ float g_zpart[KSPLIT * B_ * ZLD];
__device__ float g_z[B_ * LAT_];
__device__ float g_d[B_ * GC_];

__device__ __forceinline__ float lrelu(float v) { return v >= 0.0f ? v : 0.1f * v; }

__device__ __forceinline__ uint32_t smem_u32(const void* p) {
    return (uint32_t)__cvta_generic_to_shared(p);
}
// cp.async with L2 256B prefetch hint: same row's next k-segment = tile t+3 data
__device__ __forceinline__ void cp_async16(uint32_t dst, const void* src, int sz) {
    asm volatile("cp.async.cg.shared.global.L2::256B [%0], [%1], 16, %2;"
                 :: "r"(dst), "l"(src), "r"(sz));
}
#define CP_COMMIT() asm volatile("cp.async.commit_group;" ::: "memory")
#define CP_WAIT1()  asm volatile("cp.async.wait_group 1;" ::: "memory")
#define CP_WAIT0()  asm volatile("cp.async.wait_group 0;" ::: "memory")

// raw fp32 bits fed as tf32 operands (HW truncation; measured 4.3e-6 final err)
__device__ __forceinline__ void mma_tf32(float c[4], uint32_t a0, uint32_t a1,
                                         uint32_t a2, uint32_t a3,
                                         uint32_t b0, uint32_t b1) {
    asm volatile(
        "mma.sync.aligned.m16n8k8.row.col.f32.tf32.tf32.f32 "
        "{%0,%1,%2,%3}, {%4,%5,%6,%7}, {%8,%9}, {%0,%1,%2,%3};"
        : "+f"(c[0]), "+f"(c[1]), "+f"(c[2]), "+f"(c[3])
        : "r"(a0), "r"(a1), "r"(a2), "r"(a3), "r"(b0), "r"(b1));
}

// ---------------------------------------------------------------------------
// K1: encoder grouped conv
// ---------------------------------------------------------------------------
__global__ void __launch_bounds__(192)
enc_conv_kernel(const float* __restrict__ x, const float* __restrict__ ew,
                const float* __restrict__ eb) {
    __shared__ float sx[64 * KW_];
    const int b  = blockIdx.y;
    const int g0 = blockIdx.x * 64;
    const int ng = (G_ - g0 < 64) ? (G_ - g0) : 64;
    const int nval = ng * KW_;
    for (int i = threadIdx.x; i < nval; i += 192)
        sx[i] = x[(size_t)b * INLEN_ + (size_t)g0 * KW_ + i];
    __syncthreads();
    const int j  = threadIdx.x;
    const int gl = j / 3;
    const int c  = j - gl * 3;
    const int g  = g0 + gl;
    if (gl < ng) {
        const float* w  = ew + (size_t)g * 60 + c * 20;
        const float* xv = sx + gl * KW_;
        float acc = eb[g * 3 + c];
#pragma unroll
        for (int k = 0; k < KW_; k++) acc = fmaf(xv[k], w[k], acc);
        g_h[(size_t)b * GC_ + g * 3 + c] = lrelu(acc);
    }
}

// fragment loads for one k8 step (R11-proven conflict-free scalar LDS pattern)
#define LOAD_FRAGS(ksi, ab, bb)                                               \
    do {                                                                      \
        const int kk0_ = (ksi) * 8;                                           \
        _Pragma("unroll")                                                     \
        for (int i_ = 0; i_ < 4; i_++) {                                      \
            const float* ap_ = As + (size_t)(wm * 64 + i_ * 16 + gq) * SAK    \
                             + kk0_ + tg;                                     \
            (ab)[i_][0] = __float_as_uint(ap_[0]);                            \
            (ab)[i_][2] = __float_as_uint(ap_[4]);                            \
            (ab)[i_][1] = __float_as_uint(ap_[8 * SAK]);                      \
            (ab)[i_][3] = __float_as_uint(ap_[8 * SAK + 4]);                  \
        }                                                                     \
        _Pragma("unroll")                                                     \
        for (int j_ = 0; j_ < 4; j_++) {                                      \
            const float* wp_ = Ws + (size_t)(wn * 32 + j_ * 8 + gq) * SAK     \
                             + kk0_ + tg;                                     \
            (bb)[j_][0] = __float_as_uint(wp_[0]);                            \
            (bb)[j_][1] = __float_as_uint(wp_[4]);                            \
        }                                                                     \
    } while (0)

// ---------------------------------------------------------------------------
// tf32 mma.sync GEMM: C[128, ntile] (+)= A[128,K] x W[N,K]^T
// R11 structure + in-tile fragment double-buffering: ks+1 frags load under
// ks MMAs, hiding the 29-cyc LDS latency chain.
//   mode 0: A=g_h, C=g_zpart + by*B_*ZLD (raw split-K partial)
//   mode 1: A=g_z, C=g_d, epilogue lrelu(acc + bias[n])
// ---------------------------------------------------------------------------
__global__ void __launch_bounds__(256, 2)
gemm_tc(const float* __restrict__ Wg, const float* __restrict__ bias,
        int lda, int ldw, int ldc, int Ntot, int Ktot, int mode)
{
    extern __shared__ float smem[];
    const int tid  = threadIdx.x;
    const int lane = tid & 31;
    const int wid  = tid >> 5;
    const int gq   = lane >> 2;    // 0..7
    const int tg   = lane & 3;     // 0..3
    const int wm   = wid >> 2;     // 0..1  (M)
    const int wn   = wid & 3;      // 0..3  (N)

    const int n0 = blockIdx.x * 128;
    const int k0 = blockIdx.y * KCHUNK;
    const int k1 = (k0 + KCHUNK < Ktot) ? (k0 + KCHUNK) : Ktot;
    const int T  = (k1 - k0 + BK - 1) >> 5;

    const float* A = (mode == 0) ? g_h : g_z;
    float* C = (mode == 0) ? (g_zpart + (size_t)blockIdx.y * (B_ * (size_t)ZLD))
                           : g_d;

    const uint32_t sbase = smem_u32(smem);

    // loader (R11 proven): 1024 16B-segments per operand tile; 4 per thread.
    auto load_tile = [&](int t, int s) {
        const int kb = k0 + (t << 5);
        const uint32_t sa = sbase + (uint32_t)s * STAGE_BYTES;
        const uint32_t sw = sa + TILE_B;
#pragma unroll
        for (int u = 0; u < 4; u++) {
            const int f   = tid + u * 256;
            const int row = f >> 3;
            const int seg = f & 7;
            const int kk  = kb + seg * 4;
            const int okA = (kk + 4 <= k1) ? 16 : 0;
            const uint32_t doff = (uint32_t)(row * (SAK * 4) + seg * 16);
            cp_async16(sa + doff, okA ? (A + (size_t)row * lda + kk) : A, okA);
            const int n   = n0 + row;
            const int okW = (okA && n < Ntot) ? 16 : 0;
            cp_async16(sw + doff, okW ? (Wg + (size_t)n * ldw + kk) : Wg, okW);
        }
        CP_COMMIT();
    };

    float acc[4][4][4];
#pragma unroll
    for (int i = 0; i < 4; i++)
#pragma unroll
        for (int j = 0; j < 4; j++)
#pragma unroll
            for (int r = 0; r < 4; r++) acc[i][j][r] = 0.0f;

    load_tile(0, 0);
    if (T > 1) load_tile(1, 1);

    uint32_t af[2][4][4];
    uint32_t bf[2][4][2];

    int s = 0, sl = 2;
    for (int t = 0; t < T; t++) {
        if (t + 1 < T) { CP_WAIT1(); } else { CP_WAIT0(); }
        __syncthreads();

        const float* As = smem + (size_t)s * (STAGE_BYTES / 4);
        const float* Ws = As + TILE_F;

        // prime ks=0 fragments (critical path), then issue next tile's loads
        LOAD_FRAGS(0, af[0], bf[0]);
        if (t + 2 < T) load_tile(t + 2, sl);

#pragma unroll
        for (int ks = 0; ks < 4; ks++) {
            const int cur = ks & 1;
            const int nx  = cur ^ 1;
            if (ks < 3) LOAD_FRAGS(ks + 1, af[nx], bf[nx]);
#pragma unroll
            for (int j = 0; j < 4; j++)
#pragma unroll
                for (int i = 0; i < 4; i++)
                    mma_tf32(acc[i][j],
                             af[cur][i][0], af[cur][i][1],
                             af[cur][i][2], af[cur][i][3],
                             bf[cur][j][0], bf[cur][j][1]);
        }
        s  = (s  == NST - 1) ? 0 : s + 1;
        sl = (sl == NST - 1) ? 0 : sl + 1;
    }

    // epilogue
#pragma unroll
    for (int i = 0; i < 4; i++) {
        const int row = wm * 64 + i * 16 + gq;
#pragma unroll
        for (int j = 0; j < 4; j++) {
            const int col = n0 + wn * 32 + j * 8 + 2 * tg;
            float v0 = acc[i][j][0], v1 = acc[i][j][1];
            float v2 = acc[i][j][2], v3 = acc[i][j][3];
            if (mode == 1) {
                if (col >= Ntot) continue;
                const float b0 = bias[col], b1 = bias[col + 1];
                v0 = lrelu(v0 + b0); v1 = lrelu(v1 + b1);
                v2 = lrelu(v2 + b0); v3 = lrelu(v3 + b1);
            }
            *(float2*)(C + (size_t)row * ldc + col) = make_float2(v0, v1);
            *(float2*)(C + (size_t)(row + 8) * ldc + col) = make_float2(v2, v3);
        }
    }
}

// ---------------------------------------------------------------------------
// K3: split-K reduce + bias + leaky -> g_z
// ---------------------------------------------------------------------------
__global__ void __launch_bounds__(256)
reduce_z(const float* __restrict__ bias) {
    int idx = blockIdx.x * 256 + threadIdx.x;
    if (idx >= B_ * LAT_) return;
    int b = idx / LAT_;
    int n = idx - b * LAT_;
    float s = bias[n];
#pragma unroll
    for (int sp = 0; sp < KSPLIT; sp++)
        s += g_zpart[(size_t)sp * B_ * ZLD + (size_t)b * ZLD + n];
    g_z[idx] = lrelu(s);
}

// ---------------------------------------------------------------------------
// K5: decoder grouped conv-transpose + sigmoid (float4 vectorized)
// ---------------------------------------------------------------------------
__global__ void __launch_bounds__(256)
dec_kernel(const float* __restrict__ dw, const float* __restrict__ db,
           float* __restrict__ out) {
    int idx = blockIdx.x * 256 + threadIdx.x;
    if (idx >= B_ * G_ * 5) return;
    int b = idx / (G_ * 5);
    int r = idx - b * (G_ * 5);
    int g = r / 5;
    int q = (r - g * 5) * 4;

    const float* dd = g_d + (size_t)b * GC_ + g * 3;
    const float d0 = dd[0], d1 = dd[1], d2 = dd[2];
    const float* wb = dw + (size_t)g * 60 + q;
    const float4 w0 = *(const float4*)(wb);
    const float4 w1 = *(const float4*)(wb + 20);
    const float4 w2 = *(const float4*)(wb + 40);
    const float bs = db[g];

    float4 o;
    float a;
    a = bs + d0 * w0.x + d1 * w1.x + d2 * w2.x; o.x = 1.0f / (1.0f + __expf(-a));
    a = bs + d0 * w0.y + d1 * w1.y + d2 * w2.y; o.y = 1.0f / (1.0f + __expf(-a));
    a = bs + d0 * w0.z + d1 * w1.z + d2 * w2.z; o.z = 1.0f / (1.0f + __expf(-a));
    a = bs + d0 * w0.w + d1 * w1.w + d2 * w2.w; o.w = 1.0f / (1.0f + __expf(-a));
    *(float4*)(out + (size_t)b * INLEN_ + g * 20 + q) = o;
}

// ---------------------------------------------------------------------------
extern "C" void kernel_launch(void* const* d_in, const int* in_sizes, int n_in,
                              void* d_out, int out_size) {
    const float* x        = (const float*)d_in[0];
    const float* enc_w    = (const float*)d_in[1];
    const float* enc_b    = (const float*)d_in[2];
    const float* enc_fc_w = (const float*)d_in[3];
    const float* enc_fc_b = (const float*)d_in[4];
    const float* dec_fc_w = (const float*)d_in[5];
    const float* dec_fc_b = (const float*)d_in[6];
    const float* dec_w    = (const float*)d_in[7];
    const float* dec_b    = (const float*)d_in[8];
    float* out = (float*)d_out;

    cudaFuncSetAttribute(gemm_tc, cudaFuncAttributeMaxDynamicSharedMemorySize,
                         SMEM_DYN);

    // 1) encoder grouped conv -> g_h [128, 30000]
    enc_conv_kernel<<<dim3(157, 128), 192>>>(x, enc_w, enc_b);

    // 2) enc FC tf32 mma, split-K=15 -> g_zpart  (W=[2000,30000])
    gemm_tc<<<dim3(16, KSPLIT), 256, SMEM_DYN>>>(enc_fc_w, nullptr,
                                                 GC_, GC_, ZLD, LAT_, GC_, 0);

    // 3) reduce + bias + leaky -> g_z [128, 2000]
    reduce_z<<<(B_ * LAT_ + 255) / 256, 256>>>(enc_fc_b);

    // 4) dec FC tf32 mma, fused epilogue -> g_d [128, 30000]  (W=[30000,2000])
    gemm_tc<<<dim3(235, 1), 256, SMEM_DYN>>>(dec_fc_w, dec_fc_b,
                                             LAT_, LAT_, GC_, GC_, LAT_, 1);

    // 5) decoder conv-transpose + sigmoid -> out [128, 200000]
    dec_kernel<<<(B_ * G_ * 5 + 255) / 256, 256>>>(dec_w, dec_b, out);
}

// round 17
// speedup vs baseline: 1.2988x; 1.0873x over previous
#include <cuda_runtime.h>
#include <cstdint>

#define B_      128
#define G_      10000
#define KW_     20
#define GC_     30000
#define LAT_    2000
#define INLEN_  200000

#define KSPLIT  15
#define KCHUNK  2016          // 15*2016 >= 30000
#define ZLD     2048

#define BK      32
#define SAKH    40            // bf16 row stride: bank=(20*gq+tg)%32 = perfect perm
#define ATILE_E (128 * SAKH)              // bf16 elems per operand tile (5120)
#define ATILE_B (ATILE_E * 2)             // 10240 bytes
#define NST     3
#define STAGE_BYTES (2 * ATILE_B)         // A + W (20480)
#define SMEM_DYN    (NST * STAGE_BYTES)   // 61440

// ----- scratch (static device globals; allocation-free rule) -----
__device__ float g_h[B_ * GC_];
__device__ float g_zpart[KSPLIT * B_ * ZLD];
__device__ float g_z[B_ * LAT_];
__device__ float g_d[B_ * GC_];

__device__ __forceinline__ float lrelu(float v) { return v >= 0.0f ? v : 0.1f * v; }

__device__ __forceinline__ uint32_t smem_u32(const void* p) {
    return (uint32_t)__cvta_generic_to_shared(p);
}

// pack 2 floats -> bf16x2 (round-nearest): lo = x, hi = y  (R10-verified)
__device__ __forceinline__ uint32_t bf2(float x, float y) {
    uint32_t r;
    asm("cvt.rn.bf16x2.f32 %0, %1, %2;" : "=r"(r) : "f"(y), "f"(x));
    return r;
}

__device__ __forceinline__ void sts128(uint32_t addr, uint32_t r0, uint32_t r1,
                                       uint32_t r2, uint32_t r3) {
    asm volatile("st.shared.v4.b32 [%0], {%1, %2, %3, %4};"
                 :: "r"(addr), "r"(r0), "r"(r1), "r"(r2), "r"(r3) : "memory");
}

// bf16 m16n8k16 MMA (R10-verified fragment mapping)
__device__ __forceinline__ void mma_bf16(float c[4], const uint32_t a[4],
                                         uint32_t b0, uint32_t b1) {
    asm volatile(
        "mma.sync.aligned.m16n8k16.row.col.f32.bf16.bf16.f32 "
        "{%0,%1,%2,%3}, {%4,%5,%6,%7}, {%8,%9}, {%0,%1,%2,%3};"
        : "+f"(c[0]), "+f"(c[1]), "+f"(c[2]), "+f"(c[3])
        : "r"(a[0]), "r"(a[1]), "r"(a[2]), "r"(a[3]), "r"(b0), "r"(b1));
}

// ---------------------------------------------------------------------------
// K1: encoder grouped conv
// ---------------------------------------------------------------------------
__global__ void __launch_bounds__(192)
enc_conv_kernel(const float* __restrict__ x, const float* __restrict__ ew,
                const float* __restrict__ eb) {
    __shared__ float sx[64 * KW_];
    const int b  = blockIdx.y;
    const int g0 = blockIdx.x * 64;
    const int ng = (G_ - g0 < 64) ? (G_ - g0) : 64;
    const int nval = ng * KW_;
    for (int i = threadIdx.x; i < nval; i += 192)
        sx[i] = x[(size_t)b * INLEN_ + (size_t)g0 * KW_ + i];
    __syncthreads();
    const int j  = threadIdx.x;
    const int gl = j / 3;
    const int c  = j - gl * 3;
    const int g  = g0 + gl;
    if (gl < ng) {
        const float* w  = ew + (size_t)g * 60 + c * 20;
        const float* xv = sx + gl * KW_;
        float acc = eb[g * 3 + c];
#pragma unroll
        for (int k = 0; k < KW_; k++) acc = fmaf(xv[k], w[k], acc);
        g_h[(size_t)b * GC_ + g * 3 + c] = lrelu(acc);
    }
}

// ---------------------------------------------------------------------------
// bf16-staged mma.sync GEMM: C[128, ntile] (+)= A[128,K] x W[N,K]^T
// LDG fp32 -> cvt bf16 -> STS (halves SMEM crossbar bytes + MMA count).
// Scalar LDS.32 bf16x2 fragment loads, conflict-free via SAKH=40.
// 3-stage smem ring, 1 barrier/tile. 256 threads, tile 128x128x32, warps 2x4.
//   mode 0: A=g_h, C=g_zpart + by*B_*ZLD (raw split-K partial)
//   mode 1: A=g_z, C=g_d, epilogue lrelu(acc + bias[n])
// ---------------------------------------------------------------------------
__global__ void __launch_bounds__(256, 2)
gemm_tc(const float* __restrict__ Wg, const float* __restrict__ bias,
        int lda, int ldw, int ldc, int Ntot, int Ktot, int mode)
{
    extern __shared__ float smem[];
    const int tid  = threadIdx.x;
    const int lane = tid & 31;
    const int wid  = tid >> 5;
    const int gq   = lane >> 2;    // 0..7
    const int tg   = lane & 3;     // 0..3
    const int wm   = wid >> 2;     // 0..1  (M)
    const int wn   = wid & 3;      // 0..3  (N)

    const int n0 = blockIdx.x * 128;
    const int k0 = blockIdx.y * KCHUNK;
    const int k1 = (k0 + KCHUNK < Ktot) ? (k0 + KCHUNK) : Ktot;
    const int T  = (k1 - k0 + BK - 1) >> 5;

    const float* A = (mode == 0) ? g_h : g_z;
    float* C = (mode == 0) ? (g_zpart + (size_t)blockIdx.y * (B_ * (size_t)ZLD))
                           : g_d;

    const uint32_t sbase = smem_u32(smem);
    const float4 z4 = make_float4(0.f, 0.f, 0.f, 0.f);

    // loader: LDG 8x float4 fp32 -> 16x cvt -> 4x STS.128 bf16 per thread/tile
    auto load_tile = [&](int t, int s) {
        const int kb = k0 + (t << 5);
        const uint32_t sa = sbase + (uint32_t)s * STAGE_BYTES;
        const uint32_t sw = sa + ATILE_B;
#pragma unroll
        for (int u = 0; u < 2; u++) {
            const int f   = tid + u * 256;      // 0..511
            const int row = f >> 2;             // 0..127
            const int seg = f & 3;              // 8-float chunk
            const int kk  = kb + seg * 8;
            const bool okk = (kk + 8 <= k1);    // k1 is a multiple of 8
            const uint32_t doff = (uint32_t)(row * 80 + seg * 16);
            // A
            const float* ap = A + (size_t)row * lda + kk;
            float4 a0 = okk ? *(const float4*)(ap)     : z4;
            float4 a1 = okk ? *(const float4*)(ap + 4) : z4;
            sts128(sa + doff,
                   bf2(a0.x, a0.y), bf2(a0.z, a0.w),
                   bf2(a1.x, a1.y), bf2(a1.z, a1.w));
            // W
            const int n = n0 + row;
            const bool okw = okk && (n < Ntot);
            const float* wp = Wg + (size_t)n * ldw + kk;
            float4 w0 = okw ? *(const float4*)(wp)     : z4;
            float4 w1 = okw ? *(const float4*)(wp + 4) : z4;
            sts128(sw + doff,
                   bf2(w0.x, w0.y), bf2(w0.z, w0.w),
                   bf2(w1.x, w1.y), bf2(w1.z, w1.w));
        }
    };

    float acc[4][4][4];
#pragma unroll
    for (int i = 0; i < 4; i++)
#pragma unroll
        for (int j = 0; j < 4; j++)
#pragma unroll
            for (int r = 0; r < 4; r++) acc[i][j][r] = 0.0f;

    load_tile(0, 0);
    if (T > 1) load_tile(1, 1);

    int s = 0, sl = 2;
    for (int t = 0; t < T; t++) {
        __syncthreads();
        if (t + 2 < T) load_tile(t + 2, sl);

        const uint16_t* As = (const uint16_t*)smem + (size_t)s * (STAGE_BYTES / 2);
        const uint16_t* Ws = As + ATILE_E;
#pragma unroll
        for (int ksh = 0; ksh < 2; ksh++) {
            const int kk0 = ksh * 16 + 2 * tg;
            uint32_t af[4][4];
#pragma unroll
            for (int i = 0; i < 4; i++) {
                const uint16_t* ap = As + (size_t)(wm * 64 + i * 16 + gq) * SAKH
                                   + kk0;
                af[i][0] = *(const uint32_t*)(ap);
                af[i][1] = *(const uint32_t*)(ap + 8 * SAKH);
                af[i][2] = *(const uint32_t*)(ap + 8);
                af[i][3] = *(const uint32_t*)(ap + 8 * SAKH + 8);
            }
#pragma unroll
            for (int j = 0; j < 4; j++) {
                const uint16_t* wp = Ws + (size_t)(wn * 32 + j * 8 + gq) * SAKH
                                   + kk0;
                const uint32_t b0 = *(const uint32_t*)(wp);
                const uint32_t b1 = *(const uint32_t*)(wp + 8);
#pragma unroll
                for (int i = 0; i < 4; i++)
                    mma_bf16(acc[i][j], af[i], b0, b1);
            }
        }
        s  = (s  == NST - 1) ? 0 : s + 1;
        sl = (sl == NST - 1) ? 0 : sl + 1;
    }

    // epilogue
#pragma unroll
    for (int i = 0; i < 4; i++) {
        const int row = wm * 64 + i * 16 + gq;
#pragma unroll
        for (int j = 0; j < 4; j++) {
            const int col = n0 + wn * 32 + j * 8 + 2 * tg;
            float v0 = acc[i][j][0], v1 = acc[i][j][1];
            float v2 = acc[i][j][2], v3 = acc[i][j][3];
            if (mode == 1) {
                if (col >= Ntot) continue;
                const float b0 = bias[col], b1 = bias[col + 1];
                v0 = lrelu(v0 + b0); v1 = lrelu(v1 + b1);
                v2 = lrelu(v2 + b0); v3 = lrelu(v3 + b1);
            }
            *(float2*)(C + (size_t)row * ldc + col) = make_float2(v0, v1);
            *(float2*)(C + (size_t)(row + 8) * ldc + col) = make_float2(v2, v3);
        }
    }
}

// ---------------------------------------------------------------------------
// K3: split-K reduce + bias + leaky -> g_z
// ---------------------------------------------------------------------------
__global__ void __launch_bounds__(256)
reduce_z(const float* __restrict__ bias) {
    int idx = blockIdx.x * 256 + threadIdx.x;
    if (idx >= B_ * LAT_) return;
    int b = idx / LAT_;
    int n = idx - b * LAT_;
    float s = bias[n];
#pragma unroll
    for (int sp = 0; sp < KSPLIT; sp++)
        s += g_zpart[(size_t)sp * B_ * ZLD + (size_t)b * ZLD + n];
    g_z[idx] = lrelu(s);
}

// ---------------------------------------------------------------------------
// K5: decoder grouped conv-transpose + sigmoid (float4 vectorized)
// ---------------------------------------------------------------------------
__global__ void __launch_bounds__(256)
dec_kernel(const float* __restrict__ dw, const float* __restrict__ db,
           float* __restrict__ out) {
    int idx = blockIdx.x * 256 + threadIdx.x;
    if (idx >= B_ * G_ * 5) return;
    int b = idx / (G_ * 5);
    int r = idx - b * (G_ * 5);
    int g = r / 5;
    int q = (r - g * 5) * 4;

    const float* dd = g_d + (size_t)b * GC_ + g * 3;
    const float d0 = dd[0], d1 = dd[1], d2 = dd[2];
    const float* wb = dw + (size_t)g * 60 + q;
    const float4 w0 = *(const float4*)(wb);
    const float4 w1 = *(const float4*)(wb + 20);
    const float4 w2 = *(const float4*)(wb + 40);
    const float bs = db[g];

    float4 o;
    float a;
    a = bs + d0 * w0.x + d1 * w1.x + d2 * w2.x; o.x = 1.0f / (1.0f + __expf(-a));
    a = bs + d0 * w0.y + d1 * w1.y + d2 * w2.y; o.y = 1.0f / (1.0f + __expf(-a));
    a = bs + d0 * w0.z + d1 * w1.z + d2 * w2.z; o.z = 1.0f / (1.0f + __expf(-a));
    a = bs + d0 * w0.w + d1 * w1.w + d2 * w2.w; o.w = 1.0f / (1.0f + __expf(-a));
    *(float4*)(out + (size_t)b * INLEN_ + g * 20 + q) = o;
}

// ---------------------------------------------------------------------------
extern "C" void kernel_launch(void* const* d_in, const int* in_sizes, int n_in,
                              void* d_out, int out_size) {
    const float* x        = (const float*)d_in[0];
    const float* enc_w    = (const float*)d_in[1];
    const float* enc_b    = (const float*)d_in[2];
    const float* enc_fc_w = (const float*)d_in[3];
    const float* enc_fc_b = (const float*)d_in[4];
    const float* dec_fc_w = (const float*)d_in[5];
    const float* dec_fc_b = (const float*)d_in[6];
    const float* dec_w    = (const float*)d_in[7];
    const float* dec_b    = (const float*)d_in[8];
    float* out = (float*)d_out;

    cudaFuncSetAttribute(gemm_tc, cudaFuncAttributeMaxDynamicSharedMemorySize,
                         SMEM_DYN);

    // 1) encoder grouped conv -> g_h [128, 30000]
    enc_conv_kernel<<<dim3(157, 128), 192>>>(x, enc_w, enc_b);

    // 2) enc FC bf16 mma, split-K=15 -> g_zpart  (W=[2000,30000])
    gemm_tc<<<dim3(16, KSPLIT), 256, SMEM_DYN>>>(enc_fc_w, nullptr,
                                                 GC_, GC_, ZLD, LAT_, GC_, 0);

    // 3) reduce + bias + leaky -> g_z [128, 2000]
    reduce_z<<<(B_ * LAT_ + 255) / 256, 256>>>(enc_fc_b);

    // 4) dec FC bf16 mma, fused epilogue -> g_d [128, 30000]  (W=[30000,2000])
    gemm_tc<<<dim3(235, 1), 256, SMEM_DYN>>>(dec_fc_w, dec_fc_b,
                                             LAT_, LAT_, GC_, GC_, LAT_, 1);

    // 5) decoder conv-transpose + sigmoid -> out [128, 200000]
    dec_kernel<<<(B_ * G_ * 5 + 255) / 256, 256>>>(dec_w, dec_b, out);
}